// round 8
// baseline (speedup 1.0000x reference)
#include <cuda_runtime.h>
#include <math_constants.h>

namespace {

constexpr int TOKENS   = 16384;
constexpr int NEXP     = 64;
constexpr int KDIM     = 2048;
constexpr int K_TOP    = 6;
constexpr int TILE_M   = 64;        // tokens per block
constexpr int KC       = 16;        // k-chunk
constexpr int NCH      = KDIM / KC; // 128 chunks
constexpr int NTHREADS = 128;
constexpr int XROW     = 68;        // xs row stride (TILE_M + 4)
constexpr int WROW     = 132;       // ws row stride (2*NEXP + 4), duplicated
constexpr int LROW     = 66;        // logitsT row stride (TILE_M + 2)
constexpr float FP32_MIN_NORMAL = 1.17549435e-38f;  // 2^-126

struct __align__(16) Smem {
  union {
    struct {
      float xs[2][KC][XROW];   // [buf][k][token]      (k-major)
      float ws[2][KC][WROW];   // [buf][k][2*expert]   (duplicated {w,w})
    } mm;
    float logitsT[NEXP][LROW]; // [expert][token]
  };
};

__device__ __forceinline__ void fma2(unsigned long long& d,
                                     unsigned long long a,
                                     unsigned long long b) {
  // packed fp32x2 fused MAC: per-lane chains identical to scalar
  // sequential-k FFMA.
  asm("fma.rn.f32x2 %0, %1, %2, %0;" : "+l"(d) : "l"(a), "l"(b));
}

__device__ __forceinline__ unsigned long long ld64(const float* p) {
  // single LDS.64
  return *reinterpret_cast<const unsigned long long*>(p);
}

}  // namespace

__global__ void __launch_bounds__(NTHREADS, 2)
gate_kernel(const float* __restrict__ x, const float* __restrict__ w,
            float* __restrict__ outw, float* __restrict__ outi)
{
  __shared__ Smem sm;

  const int tid  = threadIdx.x;
  const int warp = tid >> 5;
  const int lane = tid & 31;
  const int tg   = lane >> 3;            // 0..3 : 8 consecutive lanes share tg
  const int eg   = lane & 7;             // 0..7
  // warp tile: 32 tokens x 32 experts; 4 warps cover 64x64
  const int tokbase = (warp >> 1) * 32 + tg * 8;   // thread: tokens +0..7
  const int expbase = (warp & 1) * 32 + eg * 4;    // thread: experts +0..3
  const int tile0 = blockIdx.x * TILE_M;

  const float4* __restrict__ x4 = reinterpret_cast<const float4*>(x);
  const float4* __restrict__ w4 = reinterpret_cast<const float4*>(w);
  const int rowF4 = KDIM / 4;  // 512 float4 per row

  // ---- global-load indexing (2 x-float4 + 2 w-float4 per thread/chunk) ----
  int xtok[2], xk4[2], wexp[2], wk4[2];
  long xix[2], wix[2];
#pragma unroll
  for (int i = 0; i < 2; ++i) {
    const int f = tid + i * NTHREADS;
    xtok[i] = f & 63;
    xk4[i]  = f >> 6;
    xix[i]  = (long)(tile0 + xtok[i]) * rowF4 + xk4[i];
    wexp[i] = f & 63;
    wk4[i]  = f >> 6;
    wix[i]  = (long)wexp[i] * rowF4 + wk4[i];
  }

  float4 xst[2], wst[2];

  // ---- prologue: chunk 0 -> buf 0 -----------------------------------------
#pragma unroll
  for (int i = 0; i < 2; ++i) { xst[i] = x4[xix[i]]; wst[i] = w4[wix[i]]; }

#pragma unroll
  for (int i = 0; i < 2; ++i) {
    sm.mm.xs[0][xk4[i] * 4 + 0][xtok[i]] = xst[i].x;
    sm.mm.xs[0][xk4[i] * 4 + 1][xtok[i]] = xst[i].y;
    sm.mm.xs[0][xk4[i] * 4 + 2][xtok[i]] = xst[i].z;
    sm.mm.xs[0][xk4[i] * 4 + 3][xtok[i]] = xst[i].w;
    *reinterpret_cast<float2*>(&sm.mm.ws[0][wk4[i] * 4 + 0][2 * wexp[i]]) =
        make_float2(wst[i].x, wst[i].x);
    *reinterpret_cast<float2*>(&sm.mm.ws[0][wk4[i] * 4 + 1][2 * wexp[i]]) =
        make_float2(wst[i].y, wst[i].y);
    *reinterpret_cast<float2*>(&sm.mm.ws[0][wk4[i] * 4 + 2][2 * wexp[i]]) =
        make_float2(wst[i].z, wst[i].z);
    *reinterpret_cast<float2*>(&sm.mm.ws[0][wk4[i] * 4 + 3][2 * wexp[i]]) =
        make_float2(wst[i].w, wst[i].w);
  }
  __syncthreads();

  // ---- accumulators: 4 experts x 4 token-pairs, each f32x2 -----------------
  unsigned long long acc[4][4];
#pragma unroll
  for (int e = 0; e < 4; ++e)
#pragma unroll
    for (int p = 0; p < 4; ++p) acc[e][p] = 0ULL;

  // ---- mainloop ------------------------------------------------------------
  for (int c = 0; c < NCH; ++c) {
    const int buf = c & 1;

    if (c + 1 < NCH) {
      const long off = (long)(c + 1) * (KC / 4);
#pragma unroll
      for (int i = 0; i < 2; ++i) {
        xst[i] = x4[xix[i] + off];
        wst[i] = w4[wix[i] + off];
      }
    }

#pragma unroll
    for (int kk = 0; kk < KC; ++kk) {
      const float* xrow = &sm.mm.xs[buf][kk][tokbase];
      const float* wrow = &sm.mm.ws[buf][kk][2 * expbase];

      // x: 4 token-pairs via LDS.64 — 4 distinct addrs/warp (2 per
      // half-warp) => 1 crossbar cycle each
      unsigned long long xp[4];
      xp[0] = ld64(xrow + 0);
      xp[1] = ld64(xrow + 2);
      xp[2] = ld64(xrow + 4);
      xp[3] = ld64(xrow + 6);

      // w: 4 duplicated expert-pairs via LDS.64 — 8 distinct x 8B = 64B
      // per warp => 1 crossbar cycle each
      unsigned long long wd[4];
      wd[0] = ld64(wrow + 0);
      wd[1] = ld64(wrow + 2);
      wd[2] = ld64(wrow + 4);
      wd[3] = ld64(wrow + 6);

#pragma unroll
      for (int e = 0; e < 4; ++e)
#pragma unroll
        for (int p = 0; p < 4; ++p)
          fma2(acc[e][p], wd[e], xp[p]);
    }

    if (c + 1 < NCH) {
      const int nb = buf ^ 1;
#pragma unroll
      for (int i = 0; i < 2; ++i) {
        sm.mm.xs[nb][xk4[i] * 4 + 0][xtok[i]] = xst[i].x;
        sm.mm.xs[nb][xk4[i] * 4 + 1][xtok[i]] = xst[i].y;
        sm.mm.xs[nb][xk4[i] * 4 + 2][xtok[i]] = xst[i].z;
        sm.mm.xs[nb][xk4[i] * 4 + 3][xtok[i]] = xst[i].w;
        *reinterpret_cast<float2*>(&sm.mm.ws[nb][wk4[i] * 4 + 0][2 * wexp[i]]) =
            make_float2(wst[i].x, wst[i].x);
        *reinterpret_cast<float2*>(&sm.mm.ws[nb][wk4[i] * 4 + 1][2 * wexp[i]]) =
            make_float2(wst[i].y, wst[i].y);
        *reinterpret_cast<float2*>(&sm.mm.ws[nb][wk4[i] * 4 + 2][2 * wexp[i]]) =
            make_float2(wst[i].z, wst[i].z);
        *reinterpret_cast<float2*>(&sm.mm.ws[nb][wk4[i] * 4 + 3][2 * wexp[i]]) =
            make_float2(wst[i].w, wst[i].w);
      }
    }
    __syncthreads();
  }

  // ---- epilogue: logits -> smem (transposed [expert][token]) ---------------
#pragma unroll
  for (int e = 0; e < 4; ++e)
#pragma unroll
    for (int p = 0; p < 4; ++p) {
      const float2 v = *reinterpret_cast<float2*>(&acc[e][p]);
      *reinterpret_cast<float2*>(
          &sm.logitsT[expbase + e][tokbase + 2 * p]) = v;
    }
  __syncthreads();

  // ---- per-token softmax (FTZ like XLA:GPU) + stable top-6 -----------------
  if (tid < TILE_M) {
    const int tok = tid;

    float mx = -CUDART_INF_F;
#pragma unroll 8
    for (int e = 0; e < NEXP; ++e) mx = fmaxf(mx, sm.logitsT[e][tok]);

    // cache exp values in smem (column-private) while summing
    float sum = 0.0f;
#pragma unroll 8
    for (int e = 0; e < NEXP; ++e) {
      const float p = expf(sm.logitsT[e][tok] - mx);
      sm.logitsT[e][tok] = p;
      sum += p;
    }

    float bv[K_TOP];
    int   bi[K_TOP];
#pragma unroll
    for (int j = 0; j < K_TOP; ++j) { bv[j] = -CUDART_INF_F; bi[j] = 0; }

    for (int e = 0; e < NEXP; ++e) {
      float s = sm.logitsT[e][tok] / sum;
      // XLA:GPU softmax is FTZ: subnormal scores become exactly 0.0 and
      // top_k tie-breaks among the zeros by lowest index. Replicate.
      if (s < FP32_MIN_NORMAL) s = 0.0f;
      if (s > bv[K_TOP - 1]) {
        bv[K_TOP - 1] = s;
        bi[K_TOP - 1] = e;
        // strict '>' keeps lowest-index-first ordering among equal scores
#pragma unroll
        for (int j = K_TOP - 1; j > 0; --j) {
          if (bv[j] > bv[j - 1]) {
            const float tv = bv[j]; bv[j] = bv[j - 1]; bv[j - 1] = tv;
            const int   ti = bi[j]; bi[j] = bi[j - 1]; bi[j - 1] = ti;
          }
        }
      }
    }

    const long gt = tile0 + tok;
#pragma unroll
    for (int j = 0; j < K_TOP; ++j) {
      outw[gt * K_TOP + j] = bv[j];
      outi[gt * K_TOP + j] = (float)bi[j];
    }
  }
}

extern "C" void kernel_launch(void* const* d_in, const int* in_sizes, int n_in,
                              void* d_out, int out_size) {
  const float* a = (const float*)d_in[0];
  const float* b = (const float*)d_in[1];
  const float* x = a;
  const float* w = b;
  if (n_in >= 2 && in_sizes[0] == NEXP * KDIM && in_sizes[1] == TOKENS * KDIM) {
    x = b; w = a;
  }

  float* out  = (float*)d_out;
  float* outw = out;                         // weights [16384, 6]
  float* outi = out + (long)TOKENS * K_TOP;  // indices (as float) [16384, 6]

  gate_kernel<<<TOKENS / TILE_M, NTHREADS>>>(x, w, outw, outi);
}

// round 10
// speedup vs baseline: 1.6404x; 1.6404x over previous
#include <cuda_runtime.h>
#include <math_constants.h>

namespace {

constexpr int TOKENS   = 16384;
constexpr int NEXP     = 64;
constexpr int KDIM     = 2048;
constexpr int K_TOP    = 6;
constexpr int TILE_M   = 64;        // tokens per block
constexpr int KC       = 16;        // k-chunk
constexpr int NCH      = KDIM / KC; // 128 chunks
constexpr int HCH      = NCH / 2;   // 64 chunks per k-half
constexpr int NTHREADS = 256;       // 2 k-half groups of 128
constexpr float FP32_MIN_NORMAL = 1.17549435e-38f;  // 2^-126

struct __align__(16) Smem {
  union {
    struct {
      float2 xs[2][2][TILE_M][KC + 1];  // [half][buf][token][k], x duplicated
      float  ws[2][2][KC][NEXP + 4];    // [half][buf][k][expert]
    } mm;                                // 34816 + 17408 = 52224 B
    float partial[2][TILE_M][NEXP + 2];  // [half][token][expert] = 33792 B
  };
};
constexpr int SMEM_BYTES = sizeof(Smem);

__device__ __forceinline__ void fma2(unsigned long long& d,
                                     unsigned long long a,
                                     unsigned long long b) {
  // packed fp32x2 fused MAC: per-lane chains identical to scalar
  // sequential-k FFMA.
  asm("fma.rn.f32x2 %0, %1, %2, %0;" : "+l"(d) : "l"(a), "l"(b));
}

__device__ __forceinline__ void half_bar(int kh) {
  // independent barrier per k-half group (ids 1,2; 128 threads each)
  asm volatile("bar.sync %0, %1;" :: "r"(1 + kh), "r"(128) : "memory");
}

}  // namespace

__global__ void __launch_bounds__(NTHREADS, 2)
gate_kernel(const float* __restrict__ x, const float* __restrict__ w,
            float* __restrict__ outw, float* __restrict__ outi)
{
  extern __shared__ __align__(16) char smem_raw[];
  Smem& sm = *reinterpret_cast<Smem*>(smem_raw);

  const int tid  = threadIdx.x;
  const int kh   = tid >> 7;      // k-half: 0 -> chunks 0..63, 1 -> 64..127
  const int ht   = tid & 127;     // thread id within half
  const int ecol = ht & 15;       // experts ecol*4 .. +3
  const int trow = ht >> 4;       // tokens  trow*8 .. +7
  const int tile0 = blockIdx.x * TILE_M;

  const float4* __restrict__ x4 = reinterpret_cast<const float4*>(x);
  const float4* __restrict__ w4 = reinterpret_cast<const float4*>(w);
  const int rowF4 = KDIM / 4;  // 512 float4 per row

  // ---- global-load indexing (per half, per chunk: 256 x-float4 + 256 w) ---
  const int fA = ht, fB = ht + 128;
  const int tokA = fA >> 2, k4A = fA & 3;
  const int tokB = fB >> 2, k4B = fB & 3;

  const long coff0 = (long)(kh * HCH) * (KC / 4);  // half's first chunk
  const long ixA = (long)(tile0 + tokA) * rowF4 + k4A + coff0;
  const long ixB = (long)(tile0 + tokB) * rowF4 + k4B + coff0;
  const long iwA = (long)tokA * rowF4 + k4A + coff0;  // tokA/B double as experts
  const long iwB = (long)tokB * rowF4 + k4B + coff0;

  float4 xa, xb, wa, wb;

  // ---- prologue: half's chunk 0 -> buf 0 ----------------------------------
  xa = x4[ixA]; xb = x4[ixB];
  wa = w4[iwA]; wb = w4[iwB];
  {
    sm.mm.xs[kh][0][tokA][k4A * 4 + 0] = make_float2(xa.x, xa.x);
    sm.mm.xs[kh][0][tokA][k4A * 4 + 1] = make_float2(xa.y, xa.y);
    sm.mm.xs[kh][0][tokA][k4A * 4 + 2] = make_float2(xa.z, xa.z);
    sm.mm.xs[kh][0][tokA][k4A * 4 + 3] = make_float2(xa.w, xa.w);
    sm.mm.xs[kh][0][tokB][k4B * 4 + 0] = make_float2(xb.x, xb.x);
    sm.mm.xs[kh][0][tokB][k4B * 4 + 1] = make_float2(xb.y, xb.y);
    sm.mm.xs[kh][0][tokB][k4B * 4 + 2] = make_float2(xb.z, xb.z);
    sm.mm.xs[kh][0][tokB][k4B * 4 + 3] = make_float2(xb.w, xb.w);

    sm.mm.ws[kh][0][k4A * 4 + 0][tokA] = wa.x;
    sm.mm.ws[kh][0][k4A * 4 + 1][tokA] = wa.y;
    sm.mm.ws[kh][0][k4A * 4 + 2][tokA] = wa.z;
    sm.mm.ws[kh][0][k4A * 4 + 3][tokA] = wa.w;
    sm.mm.ws[kh][0][k4B * 4 + 0][tokB] = wb.x;
    sm.mm.ws[kh][0][k4B * 4 + 1][tokB] = wb.y;
    sm.mm.ws[kh][0][k4B * 4 + 2][tokB] = wb.z;
    sm.mm.ws[kh][0][k4B * 4 + 3][tokB] = wb.w;
  }
  half_bar(kh);

  // ---- accumulators: 2 expert-pairs x 8 tokens, each f32x2 ----------------
  unsigned long long acc[2][8];
#pragma unroll
  for (int ep = 0; ep < 2; ++ep)
#pragma unroll
    for (int t = 0; t < 8; ++t) acc[ep][t] = 0ULL;

  // ---- mainloop over this half's 64 chunks (strictly ascending k) --------
  for (int c = 0; c < HCH; ++c) {
    const int buf = c & 1;

    if (c + 1 < HCH) {
      const long off = (long)(c + 1) * (KC / 4);
      xa = x4[ixA + off]; xb = x4[ixB + off];
      wa = w4[iwA + off]; wb = w4[iwB + off];
    }

#pragma unroll
    for (int kk = 0; kk < KC; ++kk) {
      const float* wrow = &sm.mm.ws[kh][buf][kk][ecol * 4];
      const unsigned long long wp0 =
          *reinterpret_cast<const unsigned long long*>(wrow);
      const unsigned long long wp1 =
          *reinterpret_cast<const unsigned long long*>(wrow + 2);
#pragma unroll
      for (int t = 0; t < 8; ++t) {
        const unsigned long long xd =
            *reinterpret_cast<const unsigned long long*>(
                &sm.mm.xs[kh][buf][trow * 8 + t][kk]);
        fma2(acc[0][t], wp0, xd);
        fma2(acc[1][t], wp1, xd);
      }
    }

    if (c + 1 < HCH) {
      const int nb = buf ^ 1;
      sm.mm.xs[kh][nb][tokA][k4A * 4 + 0] = make_float2(xa.x, xa.x);
      sm.mm.xs[kh][nb][tokA][k4A * 4 + 1] = make_float2(xa.y, xa.y);
      sm.mm.xs[kh][nb][tokA][k4A * 4 + 2] = make_float2(xa.z, xa.z);
      sm.mm.xs[kh][nb][tokA][k4A * 4 + 3] = make_float2(xa.w, xa.w);
      sm.mm.xs[kh][nb][tokB][k4B * 4 + 0] = make_float2(xb.x, xb.x);
      sm.mm.xs[kh][nb][tokB][k4B * 4 + 1] = make_float2(xb.y, xb.y);
      sm.mm.xs[kh][nb][tokB][k4B * 4 + 2] = make_float2(xb.z, xb.z);
      sm.mm.xs[kh][nb][tokB][k4B * 4 + 3] = make_float2(xb.w, xb.w);

      sm.mm.ws[kh][nb][k4A * 4 + 0][tokA] = wa.x;
      sm.mm.ws[kh][nb][k4A * 4 + 1][tokA] = wa.y;
      sm.mm.ws[kh][nb][k4A * 4 + 2][tokA] = wa.z;
      sm.mm.ws[kh][nb][k4A * 4 + 3][tokA] = wa.w;
      sm.mm.ws[kh][nb][k4B * 4 + 0][tokB] = wb.x;
      sm.mm.ws[kh][nb][k4B * 4 + 1][tokB] = wb.y;
      sm.mm.ws[kh][nb][k4B * 4 + 2][tokB] = wb.z;
      sm.mm.ws[kh][nb][k4B * 4 + 3][tokB] = wb.w;
    }
    half_bar(kh);
  }

  // ---- RACE FIX: both halves must finish reading mm before partial[]
  // (which aliases mm via the union) is written by either half. -------------
  __syncthreads();

  // ---- write this half's partial logits -----------------------------------
#pragma unroll
  for (int ep = 0; ep < 2; ++ep)
#pragma unroll
    for (int t = 0; t < 8; ++t) {
      const float2 v = *reinterpret_cast<float2*>(&acc[ep][t]);
      const int tok = trow * 8 + t;
      const int e0  = ecol * 4 + ep * 2;
      *reinterpret_cast<float2*>(&sm.partial[kh][tok][e0]) = v;
    }
  __syncthreads();

  // ---- combine halves + softmax (FTZ like XLA:GPU) + stable top-6 ---------
  if (tid < TILE_M) {
    const int tok = tid;
    float* p0 = sm.partial[0][tok];
    const float* p1 = sm.partial[1][tok];

    // combine (half0 + half1, ascending-k order) and find max
    float mx = -CUDART_INF_F;
#pragma unroll 8
    for (int e = 0; e < NEXP; ++e) {
      const float l = p0[e] + p1[e];
      p0[e] = l;
      mx = fmaxf(mx, l);
    }

    // exp + sum, caching exp values (row is thread-private)
    float sum = 0.0f;
#pragma unroll 8
    for (int e = 0; e < NEXP; ++e) {
      const float p = expf(p0[e] - mx);
      p0[e] = p;
      sum += p;
    }

    float bv[K_TOP];
    int   bi[K_TOP];
#pragma unroll
    for (int j = 0; j < K_TOP; ++j) { bv[j] = -CUDART_INF_F; bi[j] = 0; }

    for (int e = 0; e < NEXP; ++e) {
      float s = p0[e] / sum;
      // XLA:GPU softmax is FTZ: subnormal scores become exactly 0.0 and
      // top_k tie-breaks among the zeros by lowest index. Replicate.
      if (s < FP32_MIN_NORMAL) s = 0.0f;
      if (s > bv[K_TOP - 1]) {
        bv[K_TOP - 1] = s;
        bi[K_TOP - 1] = e;
        // strict '>' keeps lowest-index-first ordering among equal scores
#pragma unroll
        for (int j = K_TOP - 1; j > 0; --j) {
          if (bv[j] > bv[j - 1]) {
            const float tv = bv[j]; bv[j] = bv[j - 1]; bv[j - 1] = tv;
            const int   ti = bi[j]; bi[j] = bi[j - 1]; bi[j - 1] = ti;
          }
        }
      }
    }

    const long gt = tile0 + tok;
#pragma unroll
    for (int j = 0; j < K_TOP; ++j) {
      outw[gt * K_TOP + j] = bv[j];
      outi[gt * K_TOP + j] = (float)bi[j];
    }
  }
}

extern "C" void kernel_launch(void* const* d_in, const int* in_sizes, int n_in,
                              void* d_out, int out_size) {
  const float* a = (const float*)d_in[0];
  const float* b = (const float*)d_in[1];
  const float* x = a;
  const float* w = b;
  if (n_in >= 2 && in_sizes[0] == NEXP * KDIM && in_sizes[1] == TOKENS * KDIM) {
    x = b; w = a;
  }

  float* out  = (float*)d_out;
  float* outw = out;                         // weights [16384, 6]
  float* outi = out + (long)TOKENS * K_TOP;  // indices (as float) [16384, 6]

  // opt-in to >48KB dynamic smem (idempotent; not a stream op, capture-safe)
  static bool attr_set = false;
  if (!attr_set) {
    cudaFuncSetAttribute(gate_kernel,
                         cudaFuncAttributeMaxDynamicSharedMemorySize,
                         SMEM_BYTES);
    attr_set = true;
  }

  gate_kernel<<<TOKENS / TILE_M, NTHREADS, SMEM_BYTES>>>(x, w, outw, outi);
}